// round 2
// baseline (speedup 1.0000x reference)
#include <cuda_runtime.h>
#include <math.h>

#define NB 128
#define NR 4096
#define ND 256

// Scratch (device globals — no allocation allowed)
__device__ float g_qn[NB * ND];     // normalized query vectors  [B, D]
__device__ float g_sims[NB * NR];   // cosine sims               [B, R]

// ---------------------------------------------------------------------------
// Kernel 0: per-sample query gather + normalize. grid=B, block=D(=256).
// ---------------------------------------------------------------------------
__global__ void k_qnorm(const float* __restrict__ reps,
                        const int* __restrict__ qrel) {
    int b = blockIdx.x;
    int t = threadIdx.x;
    int qidx = qrel[b];
    qidx = max(0, min(NR - 1, qidx));   // defensive clamp
    const float* q = reps + ((size_t)b * NR + (size_t)qidx) * ND;
    float v = q[t];
    float s = v * v;
    #pragma unroll
    for (int o = 16; o > 0; o >>= 1) s += __shfl_down_sync(0xffffffffu, s, o);
    __shared__ float red[8];
    __shared__ float norm_s;
    if ((t & 31) == 0) red[t >> 5] = s;
    __syncthreads();
    if (t == 0) {
        float x = 0.f;
        #pragma unroll
        for (int i = 0; i < 8; i++) x += red[i];
        norm_s = fmaxf(sqrtf(x), 1e-12f);
    }
    __syncthreads();
    g_qn[b * ND + t] = v / norm_s;
}

// ---------------------------------------------------------------------------
// Kernel 1: fused full-tensor copy + per-row cosine sim vs qn.
// One warp per row. Each lane: 2x float4 load + 2x float4 store.
// grid = (NR/8, NB), block = 256 (8 warps = 8 rows).
// ---------------------------------------------------------------------------
__global__ void k_main(const float4* __restrict__ reps,
                       float4* __restrict__ out) {
    int b    = blockIdx.y;
    int warp = threadIdx.x >> 5;
    int lane = threadIdx.x & 31;
    int row  = blockIdx.x * 8 + warp;

    __shared__ float4 qn_s[ND / 4];   // 64 float4 = 1KB
    if (threadIdx.x < ND / 4) {
        qn_s[threadIdx.x] =
            reinterpret_cast<const float4*>(g_qn)[b * (ND / 4) + threadIdx.x];
    }
    __syncthreads();

    size_t base = ((size_t)b * NR + (size_t)row) * (ND / 4);
    float dot = 0.f, ss = 0.f;
    #pragma unroll
    for (int k = 0; k < 2; k++) {
        int idx = lane + 32 * k;
        float4 v = reps[base + idx];
        out[base + idx] = v;                       // the mandatory output copy
        float4 qv = qn_s[idx];
        dot += v.x * qv.x + v.y * qv.y + v.z * qv.z + v.w * qv.w;
        ss  += v.x * v.x  + v.y * v.y  + v.z * v.z  + v.w * v.w;
    }
    #pragma unroll
    for (int o = 16; o > 0; o >>= 1) {
        dot += __shfl_down_sync(0xffffffffu, dot, o);
        ss  += __shfl_down_sync(0xffffffffu, ss,  o);
    }
    if (lane == 0) {
        float nrm = fmaxf(sqrtf(ss), 1e-12f);
        g_sims[(size_t)b * NR + row] = dot / nrm;
    }
}

// ---------------------------------------------------------------------------
// Kernel 2: per-sample masked softmax + weighted combine; writes 1 row.
// grid = B, block = 256 (thread t = output dim t).
// ---------------------------------------------------------------------------
__global__ void k_final(const float* __restrict__ reps,
                        float* __restrict__ out,
                        const int* __restrict__ qrel,
                        const float* __restrict__ thr_raw,
                        const float* __restrict__ str_raw,
                        const float* __restrict__ wscale,
                        const float* __restrict__ temp_p) {
    __shared__ float s_sims[NR];     // 16 KB
    __shared__ int   s_idx[NR];      // 16 KB (compacted masked indices)
    __shared__ int   s_cnt;
    __shared__ float s_redA[8];
    __shared__ float s_redB[8];
    __shared__ float s_Z, s_S;

    int b = blockIdx.x;
    int t = threadIdx.x;
    int qidx = qrel[b];
    qidx = max(0, min(NR - 1, qidx));   // defensive clamp

    float threshold = 1.f / (1.f + expf(-thr_raw[0]));
    float strength  = 0.2f / (1.f + expf(-str_raw[0]));
    float ws        = wscale[0];
    float temp      = fminf(fmaxf(temp_p[0], 0.1f), 10.f);

    if (t == 0) s_cnt = 0;
    __syncthreads();

    const float* simsg = g_sims + (size_t)b * NR;
    float lmax = -3e38f;
    for (int i = t; i < NR; i += 256) {
        float s = (i == qidx) ? -1.0f : simsg[i];
        s_sims[i] = s;
        if (s > threshold) {
            int p = atomicAdd(&s_cnt, 1);
            s_idx[p] = i;
            lmax = fmaxf(lmax, s);
        }
    }
    #pragma unroll
    for (int o = 16; o > 0; o >>= 1)
        lmax = fmaxf(lmax, __shfl_down_sync(0xffffffffu, lmax, o));
    if ((t & 31) == 0) s_redA[t >> 5] = lmax;
    __syncthreads();

    int cnt = s_cnt;
    size_t qoff = ((size_t)b * NR + (size_t)qidx) * ND;

    if (cnt == 0) {
        // no valid neighbor: row stays q (matches has_valid=false branch)
        out[qoff + t] = reps[qoff + t];
        return;
    }

    if (t == 0) {
        float x = s_redA[0];
        #pragma unroll
        for (int i = 1; i < 8; i++) x = fmaxf(x, s_redA[i]);
        s_redA[0] = x;
    }
    __syncthreads();
    float m = s_redA[0] / temp;   // max logit over masked entries

    // Z = softmax denom over masked; S = sum of pre-normalized adjusted weights
    float lZ = 0.f, lS = 0.f;
    for (int j = t; j < cnt; j += 256) {
        float s  = s_sims[s_idx[j]];
        float e  = expf(s / temp - m);
        float sw = 1.f / (1.f + expf(-(s - threshold) * 10.f));
        lZ += e;
        lS += e * sw * (1.f + ws * s);
    }
    #pragma unroll
    for (int o = 16; o > 0; o >>= 1) {
        lZ += __shfl_down_sync(0xffffffffu, lZ, o);
        lS += __shfl_down_sync(0xffffffffu, lS, o);
    }
    if ((t & 31) == 0) { s_redA[t >> 5] = lZ; s_redB[t >> 5] = lS; }
    __syncthreads();
    if (t == 0) {
        float z = 0.f, sS = 0.f;
        #pragma unroll
        for (int i = 0; i < 8; i++) { z += s_redA[i]; sS += s_redB[i]; }
        s_Z = z; s_S = sS;
    }
    __syncthreads();
    float Z = s_Z, S = s_S;
    // adjusted_i = (e_i*sw_i*(1+ws*s_i)/Z) / (S/Z + 1e-8)
    float scale = 1.f / (Z * (S / Z + 1e-8f));

    const float* rb = reps + (size_t)b * NR * ND;
    float acc = 0.f;
    for (int j = 0; j < cnt; j++) {
        int i = s_idx[j];
        float s  = s_sims[i];
        float e  = expf(s / temp - m);
        float sw = 1.f / (1.f + expf(-(s - threshold) * 10.f));
        float a  = e * sw * (1.f + ws * s) * scale;
        acc += a * rb[(size_t)i * ND + t];
    }

    float q = reps[qoff + t];
    out[qoff + t] = (1.f - strength) * q + strength * acc;
}

// ---------------------------------------------------------------------------
extern "C" void kernel_launch(void* const* d_in, const int* in_sizes, int n_in,
                              void* d_out, int out_size) {
    const float* reps  = (const float*)d_in[0];
    const int*   qrel  = (const int*)d_in[1];
    const float* thr   = (const float*)d_in[2];
    const float* str   = (const float*)d_in[3];
    const float* wsc   = (const float*)d_in[4];
    const float* tmp   = (const float*)d_in[5];
    float*       out   = (float*)d_out;

    k_qnorm<<<NB, ND>>>(reps, qrel);

    dim3 grid(NR / 8, NB);
    k_main<<<grid, 256>>>(reinterpret_cast<const float4*>(reps),
                          reinterpret_cast<float4*>(out));

    k_final<<<NB, 256>>>(reps, out, qrel, thr, str, wsc, tmp);
}